// round 16
// baseline (speedup 1.0000x reference)
#include <cuda_runtime.h>
#include <cstdint>
#include <math.h>

#define BB 16
#define NN 325
#define DD 64
#define HH 4
#define STEPS 12
#define MAXD 64
#define CLX 16
#define TPB 384
#define NWARP (TPB/32)   // 12
#define RPC 21           // rows per CTA: ranks 0-14 -> 21, rank 15 -> 10
#define QSLOT 2          // rows per warp (rows 2w, 2w+1)

// ---- dynamic smem layout (float offsets), float4 areas 16B-aligned ----
#define OFF_W     0        // 8192
#define OFF_X     8192     // 1344
#define OFF_AL    9536     // 12*2*64*4 = 6144
#define OFF_ES    15680    // 96
#define OFF_AS    15776    // 128
#define OFF_AD    15904    // 128
#define OFF_W2    16032    // 64
#define OFF_B1    16096    // 64
#define OFF_CNT   16160    // 32
#define OFF_IDX   16192    // 1344
#define SMEM_FLOATS 17536
#define SMEM_BYTES (SMEM_FLOATS*4)   // 70144 B -> 2 CTAs/SM fit

// ---------------- global scratch (static: no allocations) ----------------
__device__ float g_h  [2][BB*NN*DD];
__device__ float g_ed4[2][BB*NN*HH];    // interleaved: [node*4 + head]
__device__ float g_W1t[DD*DD];          // W1 transposed: [c*64 + k]
__device__ int   g_adj_cnt[NN];
__device__ int   g_adj_idx[NN*MAXD];

// ---------------- prep: adjacency CSR (ordered, zero-padded) + W1^T ------
__global__ void prep_kernel(const float* __restrict__ graph,
                            const float* __restrict__ W1)
{
    int gt = blockIdx.x * blockDim.x + threadIdx.x;
    for (int i = gt; i < DD*DD; i += gridDim.x * blockDim.x)
        g_W1t[(i & 63) * DD + (i >> 6)] = W1[i];

    int gwarp = gt >> 5;
    int lane  = threadIdx.x & 31;
    if (gwarp >= NN) return;
    const int i = gwarp;
    const float* row = graph + (size_t)i * NN;
    int c = 0;
    for (int j0 = 0; j0 < NN; j0 += 32) {
        int j = j0 + lane;
        bool v = (j < NN) && (row[j] > 0.9f || j == i);
        unsigned m = __ballot_sync(0xffffffffu, v);
        if (v) {
            int pos = c + __popc(m & ((1u << lane) - 1u));
            if (pos < MAXD) g_adj_idx[i * MAXD + pos] = j;
        }
        c += __popc(m);
    }
    int cc = (c > MAXD) ? MAXD : c;
    // pad tail with node 0 (alpha is forced to 0 there)
    for (int p = cc + lane; p < MAXD; p += 32)
        g_adj_idx[i * MAXD + p] = 0;
    if (lane == 0) g_adj_cnt[i] = cc;
}

__device__ __forceinline__ void cluster_sync_rel()
{
    asm volatile("fence.acq_rel.cluster;" ::: "memory");
    asm volatile("barrier.cluster.arrive.aligned;" ::: "memory");
    asm volatile("barrier.cluster.wait.aligned;"   ::: "memory");
}

__device__ __forceinline__ float f4c(const float4& v, int kk)
{
    return (kk == 0) ? v.x : (kk == 1) ? v.y : (kk == 2) ? v.z : v.w;
}

// ---------------- readout: out = tanh(row@W1 + b1) @ W2 + b2 -------------
__device__ __forceinline__ void warp_readout(
    const float* __restrict__ rb, const float* __restrict__ sB1,
    const float* __restrict__ sW2v, float bias2,
    float* __restrict__ outp, int lane)
{
    const float4* W1t4 = reinterpret_cast<const float4*>(g_W1t);
    float s0 = sB1[lane], s1 = sB1[lane + 32];
    #pragma unroll
    for (int k4 = 0; k4 < 16; ++k4) {
        float4 yv = reinterpret_cast<const float4*>(rb)[k4];
        float4 w0 = W1t4[lane * 16 + k4];
        float4 w1 = W1t4[(lane + 32) * 16 + k4];
        s0 += yv.x*w0.x + yv.y*w0.y + yv.z*w0.z + yv.w*w0.w;
        s1 += yv.x*w1.x + yv.y*w1.y + yv.z*w1.z + yv.w*w1.w;
    }
    float t = tanhf(s0) * sW2v[lane] + tanhf(s1) * sW2v[lane + 32];
    #pragma unroll
    for (int off = 16; off; off >>= 1)
        t += __shfl_xor_sync(0xffffffffu, t, off);
    if (lane == 0) *outp = t + bias2;
}

// ---------------- main: one 16-CTA cluster per batch (2 CTAs/SM) ----------
__global__ void __launch_bounds__(TPB, 1) __cluster_dims__(CLX, 1, 1)
ode_kernel(const float* __restrict__ y0,
           const float* __restrict__ Wg,
           const float* __restrict__ a_src,
           const float* __restrict__ a_dst,
           const float* __restrict__ b1,
           const float* __restrict__ W2,
           const float* __restrict__ b2,
           float* __restrict__ out)
{
    extern __shared__ float sm[];
    float* sW    = sm + OFF_W;
    float* sX    = sm + OFF_X;
    float* sAl   = sm + OFF_AL;
    float* sEs   = sm + OFF_ES;
    float* sAS   = sm + OFF_AS;
    float* sAD   = sm + OFF_AD;
    float* sW2v  = sm + OFF_W2;
    float* sB1   = sm + OFF_B1;
    int*   sCnt  = (int*)(sm + OFF_CNT);
    int*   sIdx  = (int*)(sm + OFF_IDX);

    const int b    = blockIdx.x / CLX;
    const int rank = blockIdx.x % CLX;
    const int tid  = threadIdx.x;
    const int wid  = tid >> 5;
    const int lane = tid & 31;
    const int hsel = lane >> 3;          // head owned by this lane
    const int base  = rank * RPC;
    const int nrows = (rank == CLX - 1) ? (NN - base) : RPC;

    for (int i = tid; i < 2*DD*DD; i += TPB) sW[i] = Wg[i];
    for (int i = tid; i < 2*DD;    i += TPB) { sAS[i] = a_src[i]; sAD[i] = a_dst[i]; }
    for (int i = tid; i < DD;      i += TPB) { sW2v[i] = W2[i]; sB1[i] = b1[i]; }
    for (int i = tid; i < nrows;   i += TPB) sCnt[i] = g_adj_cnt[base + i];
    for (int i = tid; i < nrows*MAXD; i += TPB)
        sIdx[i] = g_adj_idx[base*MAXD + i];
    const float bias2 = b2[0];

    const size_t bo = (size_t)b * NN * DD;

    // warp owns rows 2*wid, 2*wid+1 in ALL phases; q = row slot
    float yR[QSLOT][2], accR[QSLOT][2];

    __syncthreads();
    // ---- init y/x (own rows, lane owns channels 2l, 2l+1) ----
    #pragma unroll
    for (int q = 0; q < QSLOT; ++q) {
        const int r = 2*wid + q;
        if (r < nrows) {
            const size_t ro = bo + (size_t)(base + r) * DD;
            float2 yv = *reinterpret_cast<const float2*>(y0 + ro + 2*lane);
            yR[q][0] = yv.x; yR[q][1] = yv.y;
            *reinterpret_cast<float2*>(sX + r*DD + 2*lane) = yv;
        }
    }
    __syncthreads();
    // ---- t=0 readout (from sX, warp-strided) ----
    for (int r = wid; r < nrows; r += NWARP)
        warp_readout(sX + r*DD, sB1, sW2v, bias2,
                     out + ((size_t)(b*(STEPS+1) + 0))*NN + base + r, lane);

    for (int s = 0; s < STEPS; ++s) {
        const float dt = (float)(s+1)*0.1f - (float)s*0.1f;
        for (int st = 0; st < 4; ++st) {
            for (int l = 0; l < 2; ++l) {
                // ======= Phase A: h = x@W, e_src, e_dst (own rows only) ===
                {
                    const float* Wl = sW + l*DD*DD;
                    const float2* w2p = reinterpret_cast<const float2*>(Wl);
                    const int r0 = wid * 2;
                    if (r0 < nrows) {
                        int rl0 = r0;
                        int rl1 = (r0 + 1 > nrows-1) ? nrows-1 : r0 + 1;
                        float a0x=0,a0y=0,a1x=0,a1y=0;
                        const float4* x4 = reinterpret_cast<const float4*>(sX);
                        #pragma unroll 4
                        for (int k4 = 0; k4 < 16; ++k4) {
                            float4 x0 = x4[rl0*16 + k4];
                            float4 x1 = x4[rl1*16 + k4];
                            #pragma unroll
                            for (int kk = 0; kk < 4; ++kk) {
                                float2 w = w2p[(k4*4+kk)*32 + lane];
                                float c0 = f4c(x0,kk), c1 = f4c(x1,kk);
                                a0x += c0*w.x; a0y += c0*w.y;
                                a1x += c1*w.x; a1y += c1*w.y;
                            }
                        }
                        float ax[QSLOT] = {a0x, a1x};
                        float ay[QSLOT] = {a0y, a1y};
                        #pragma unroll
                        for (int q = 0; q < QSLOT; ++q) {
                            if (r0 + q >= nrows) break;
                            const int row = base + r0 + q;
                            float* hp = g_h[l] + bo + (size_t)row*DD;
                            __stcg(reinterpret_cast<float2*>(hp + 2*lane),
                                   make_float2(ax[q], ay[q]));
                            float ves = ax[q]*sAS[l*DD + 2*lane] + ay[q]*sAS[l*DD + 2*lane + 1];
                            float ved = ax[q]*sAD[l*DD + 2*lane] + ay[q]*sAD[l*DD + 2*lane + 1];
                            #pragma unroll
                            for (int off = 4; off; off >>= 1) {
                                ves += __shfl_down_sync(0xffffffffu, ves, off, 8);
                                ved += __shfl_down_sync(0xffffffffu, ved, off, 8);
                            }
                            if ((lane & 7) == 0) {
                                sEs[(r0 + q)*4 + hsel] = ves;
                                __stcg(g_ed4[l] + ((size_t)b*NN + row)*4 + hsel, ved);
                            }
                        }
                    }
                }
                cluster_sync_rel();
                // ======= softmax: 2 rows fused (no shift, ed via L2) ======
                {
                    const float4* edg = reinterpret_cast<const float4*>(
                        g_ed4[l] + (size_t)b*NN*HH);
                    const int r0 = wid * 2;
                    if (r0 < nrows) {
                        const bool hasB = (r0 + 1 < nrows);
                        const int cntA = sCnt[r0];
                        const int cntB = hasB ? sCnt[r0 + 1] : 0;
                        const int c8A = (cntA + 7) & ~7;
                        const int c8B = (cntB + 7) & ~7;
                        const int cmax = (c8A > c8B) ? c8A : c8B;
                        const int* idxA = sIdx + r0 * MAXD;
                        const int* idxB = sIdx + (hasB ? (r0 + 1) : r0) * MAXD;
                        float4* awA = reinterpret_cast<float4*>(sAl)
                                    + (wid*QSLOT + 0) * MAXD;
                        float4* awB = reinterpret_cast<float4*>(sAl)
                                    + (wid*QSLOT + 1) * MAXD;
                        float4 esA = reinterpret_cast<const float4*>(sEs)[r0];
                        float4 esB = hasB
                            ? reinterpret_cast<const float4*>(sEs)[r0 + 1] : esA;
                        for (int j0 = lane; j0 < cmax; j0 += 32) {
                            if (j0 < c8A) {
                                int j = idxA[j0];
                                float4 ev = __ldcg(edg + j);
                                float e0 = esA.x + ev.x; e0 = fmaxf(e0, 0.2f*e0);
                                float e1 = esA.y + ev.y; e1 = fmaxf(e1, 0.2f*e1);
                                float e2 = esA.z + ev.z; e2 = fmaxf(e2, 0.2f*e2);
                                float e3 = esA.w + ev.w; e3 = fmaxf(e3, 0.2f*e3);
                                float p0 = __expf(e0), p1 = __expf(e1);
                                float p2 = __expf(e2), p3 = __expf(e3);
                                if (j0 >= cntA) { p0=0.f; p1=0.f; p2=0.f; p3=0.f; }
                                awA[j0] = make_float4(p0, p1, p2, p3);
                            }
                            if (hasB && j0 < c8B) {
                                int j = idxB[j0];
                                float4 ev = __ldcg(edg + j);
                                float e0 = esB.x + ev.x; e0 = fmaxf(e0, 0.2f*e0);
                                float e1 = esB.y + ev.y; e1 = fmaxf(e1, 0.2f*e1);
                                float e2 = esB.z + ev.z; e2 = fmaxf(e2, 0.2f*e2);
                                float e3 = esB.w + ev.w; e3 = fmaxf(e3, 0.2f*e3);
                                float p0 = __expf(e0), p1 = __expf(e1);
                                float p2 = __expf(e2), p3 = __expf(e3);
                                if (j0 >= cntB) { p0=0.f; p1=0.f; p2=0.f; p3=0.f; }
                                awB[j0] = make_float4(p0, p1, p2, p3);
                            }
                        }
                    }
                }
                // ======= Phase B: SpMM from L2 (h via __ldcg, unroll 8) ===
                {
                    const float2* hg = reinterpret_cast<const float2*>(g_h[l] + bo);
                    #pragma unroll
                    for (int q = 0; q < QSLOT; ++q) {
                        const int r = 2*wid + q;
                        if (r >= nrows) break;
                        const int cnt8 = (sCnt[r] + 7) & ~7;
                        const int* idxr = sIdx + r * MAXD;
                        const float* awf = sAl + (wid*QSLOT + q) * MAXD * 4;
                        float acc0 = 0.f, acc1 = 0.f, ssum = 0.f;
                        for (int j0 = 0; j0 < cnt8; j0 += 8) {
                            int jj[8]; float al[8]; float2 hv[8];
                            #pragma unroll
                            for (int u = 0; u < 8; ++u) jj[u] = idxr[j0+u];
                            #pragma unroll
                            for (int u = 0; u < 8; ++u)
                                al[u] = awf[(j0+u)*4 + hsel];
                            #pragma unroll
                            for (int u = 0; u < 8; ++u)
                                hv[u] = __ldcg(hg + jj[u]*32 + lane);
                            #pragma unroll
                            for (int u = 0; u < 8; ++u) {
                                acc0 += al[u]*hv[u].x;
                                acc1 += al[u]*hv[u].y;
                                ssum += al[u];
                            }
                        }
                        const float inv = 1.f / ssum;
                        float k0 = acc0 * inv;
                        float k1 = acc1 * inv;
                        // ---- fused epilogue (registers -> sX, own row) ----
                        float2* xr2 = reinterpret_cast<float2*>(sX + r*DD) + lane;
                        if (l == 0) {
                            float2 xv;
                            xv.x = (k0 > 0.f) ? k0 : (__expf(k0) - 1.f);
                            xv.y = (k1 > 0.f) ? k1 : (__expf(k1) - 1.f);
                            *xr2 = xv;
                        } else {
                            if (st == 0) { accR[q][0] = k0; accR[q][1] = k1; }
                            else {
                                float w = (st == 3) ? 1.f : 2.f;
                                accR[q][0] += w * k0; accR[q][1] += w * k1;
                            }
                            if (st < 3) {
                                float cc = (st == 2) ? dt : 0.5f * dt;
                                *xr2 = make_float2(yR[q][0] + cc * k0,
                                                   yR[q][1] + cc * k1);
                            } else {
                                yR[q][0] += dt * (1.f/6.f) * accR[q][0];
                                yR[q][1] += dt * (1.f/6.f) * accR[q][1];
                                *xr2 = make_float2(yR[q][0], yR[q][1]);
                            }
                        }
                    }
                }
            } // l
        } // st
        // ---- readout for t = s+1 (sX holds y; cross-warp read) ----
        __syncthreads();
        for (int r = wid; r < nrows; r += NWARP)
            warp_readout(sX + r*DD, sB1, sW2v, bias2,
                         out + ((size_t)(b*(STEPS+1) + s + 1))*NN + base + r, lane);
        // next cluster barrier orders these reads vs future sX writes
    } // s
}

extern "C" void kernel_launch(void* const* d_in, const int* in_sizes, int n_in,
                              void* d_out, int out_size)
{
    const float* y0    = (const float*)d_in[0];
    const float* graph = (const float*)d_in[1];
    const float* Wg    = (const float*)d_in[2];
    const float* a_src = (const float*)d_in[3];
    const float* a_dst = (const float*)d_in[4];
    const float* W1    = (const float*)d_in[5];
    const float* b1    = (const float*)d_in[6];
    const float* W2    = (const float*)d_in[7];
    const float* b2    = (const float*)d_in[8];
    float* out = (float*)d_out;

    cudaFuncSetAttribute(ode_kernel,
                         cudaFuncAttributeMaxDynamicSharedMemorySize, SMEM_BYTES);
    cudaFuncSetAttribute(ode_kernel,
                         cudaFuncAttributeNonPortableClusterSizeAllowed, 1);
    prep_kernel<<<41, 256>>>(graph, W1);
    ode_kernel<<<BB*CLX, TPB, SMEM_BYTES>>>(y0, Wg, a_src, a_dst, b1, W2, b2, out);
}

// round 17
// speedup vs baseline: 1.1317x; 1.1317x over previous
#include <cuda_runtime.h>
#include <cstdint>
#include <math.h>

#define BB 16
#define NN 325
#define DD 64
#define HH 4
#define STEPS 12
#define MAXD 64
#define CLX 16
#define TPB 384
#define NWARP (TPB/32)   // 12
#define RPC 21           // rows per CTA: ranks 0-14 -> 21, rank 15 -> 10
#define QSLOT 2          // rows per warp (rows 2w, 2w+1)

// ---- dynamic smem layout (float offsets), float4 areas 16B-aligned ----
#define OFF_W     0        // 8192
#define OFF_X     8192     // 1344
#define OFF_AL    9536     // 12*2*64*4 = 6144
#define OFF_ES    15680    // 96
#define OFF_AS    15776    // 128
#define OFF_AD    15904    // 128
#define OFF_W2    16032    // 64
#define OFF_B1    16096    // 64
#define OFF_CNT   16160    // 32
#define OFF_IDX   16192    // 1344
#define SMEM_FLOATS 17536
#define SMEM_BYTES (SMEM_FLOATS*4)   // 70144 B -> 2 CTAs/SM fit

// ---------------- global scratch (static: no allocations) ----------------
__device__ float g_h  [2][BB*NN*DD];
__device__ float g_ed4[2][BB*NN*HH];    // interleaved: [node*4 + head]
__device__ float g_W1t[DD*DD];          // W1 transposed: [c*64 + k]
__device__ int   g_adj_cnt[NN];
__device__ int   g_adj_idx[NN*MAXD];

// ---------------- prep: adjacency CSR (ordered, zero-padded) + W1^T ------
__global__ void prep_kernel(const float* __restrict__ graph,
                            const float* __restrict__ W1)
{
    int gt = blockIdx.x * blockDim.x + threadIdx.x;
    for (int i = gt; i < DD*DD; i += gridDim.x * blockDim.x)
        g_W1t[(i & 63) * DD + (i >> 6)] = W1[i];

    int gwarp = gt >> 5;
    int lane  = threadIdx.x & 31;
    if (gwarp >= NN) return;
    const int i = gwarp;
    const float* row = graph + (size_t)i * NN;
    int c = 0;
    for (int j0 = 0; j0 < NN; j0 += 32) {
        int j = j0 + lane;
        bool v = (j < NN) && (row[j] > 0.9f || j == i);
        unsigned m = __ballot_sync(0xffffffffu, v);
        if (v) {
            int pos = c + __popc(m & ((1u << lane) - 1u));
            if (pos < MAXD) g_adj_idx[i * MAXD + pos] = j;
        }
        c += __popc(m);
    }
    int cc = (c > MAXD) ? MAXD : c;
    // pad tail with node 0 (alpha is forced to 0 there)
    for (int p = cc + lane; p < MAXD; p += 32)
        g_adj_idx[i * MAXD + p] = 0;
    if (lane == 0) g_adj_cnt[i] = cc;
}

__device__ __forceinline__ void cluster_sync_rel()
{
    asm volatile("fence.acq_rel.cluster;" ::: "memory");
    asm volatile("barrier.cluster.arrive.aligned;" ::: "memory");
    asm volatile("barrier.cluster.wait.aligned;"   ::: "memory");
}

__device__ __forceinline__ float f4c(const float4& v, int kk)
{
    return (kk == 0) ? v.x : (kk == 1) ? v.y : (kk == 2) ? v.z : v.w;
}

// ---------------- readout: out = tanh(row@W1 + b1) @ W2 + b2 -------------
__device__ __forceinline__ void warp_readout(
    const float* __restrict__ rb, const float* __restrict__ sB1,
    const float* __restrict__ sW2v, float bias2,
    float* __restrict__ outp, int lane)
{
    const float4* W1t4 = reinterpret_cast<const float4*>(g_W1t);
    float s0 = sB1[lane], s1 = sB1[lane + 32];
    #pragma unroll
    for (int k4 = 0; k4 < 16; ++k4) {
        float4 yv = reinterpret_cast<const float4*>(rb)[k4];
        float4 w0 = W1t4[lane * 16 + k4];
        float4 w1 = W1t4[(lane + 32) * 16 + k4];
        s0 += yv.x*w0.x + yv.y*w0.y + yv.z*w0.z + yv.w*w0.w;
        s1 += yv.x*w1.x + yv.y*w1.y + yv.z*w1.z + yv.w*w1.w;
    }
    float t = tanhf(s0) * sW2v[lane] + tanhf(s1) * sW2v[lane + 32];
    #pragma unroll
    for (int off = 16; off; off >>= 1)
        t += __shfl_xor_sync(0xffffffffu, t, off);
    if (lane == 0) *outp = t + bias2;
}

// ---------------- main: one 16-CTA cluster per batch (2 CTAs/SM) ----------
__global__ void __launch_bounds__(TPB, 2) __cluster_dims__(CLX, 1, 1)
ode_kernel(const float* __restrict__ y0,
           const float* __restrict__ Wg,
           const float* __restrict__ a_src,
           const float* __restrict__ a_dst,
           const float* __restrict__ b1,
           const float* __restrict__ W2,
           const float* __restrict__ b2,
           float* __restrict__ out)
{
    extern __shared__ float sm[];
    float* sW    = sm + OFF_W;
    float* sX    = sm + OFF_X;
    float* sAl   = sm + OFF_AL;
    float* sEs   = sm + OFF_ES;
    float* sAS   = sm + OFF_AS;
    float* sAD   = sm + OFF_AD;
    float* sW2v  = sm + OFF_W2;
    float* sB1   = sm + OFF_B1;
    int*   sCnt  = (int*)(sm + OFF_CNT);
    int*   sIdx  = (int*)(sm + OFF_IDX);

    const int b    = blockIdx.x / CLX;
    const int rank = blockIdx.x % CLX;
    const int tid  = threadIdx.x;
    const int wid  = tid >> 5;
    const int lane = tid & 31;
    const int hsel = lane >> 3;          // head owned by this lane
    const int base  = rank * RPC;
    const int nrows = (rank == CLX - 1) ? (NN - base) : RPC;

    for (int i = tid; i < 2*DD*DD; i += TPB) sW[i] = Wg[i];
    for (int i = tid; i < 2*DD;    i += TPB) { sAS[i] = a_src[i]; sAD[i] = a_dst[i]; }
    for (int i = tid; i < DD;      i += TPB) { sW2v[i] = W2[i]; sB1[i] = b1[i]; }
    for (int i = tid; i < nrows;   i += TPB) sCnt[i] = g_adj_cnt[base + i];
    for (int i = tid; i < nrows*MAXD; i += TPB)
        sIdx[i] = g_adj_idx[base*MAXD + i];
    const float bias2 = b2[0];

    const size_t bo = (size_t)b * NN * DD;

    // warp owns rows 2*wid, 2*wid+1 in ALL phases; q = row slot
    float yR[QSLOT][2], accR[QSLOT][2];

    __syncthreads();
    // ---- init y/x (own rows, lane owns channels 2l, 2l+1) ----
    #pragma unroll
    for (int q = 0; q < QSLOT; ++q) {
        const int r = 2*wid + q;
        if (r < nrows) {
            const size_t ro = bo + (size_t)(base + r) * DD;
            float2 yv = *reinterpret_cast<const float2*>(y0 + ro + 2*lane);
            yR[q][0] = yv.x; yR[q][1] = yv.y;
            *reinterpret_cast<float2*>(sX + r*DD + 2*lane) = yv;
        }
    }
    __syncthreads();
    // ---- t=0 readout (from sX, warp-strided) ----
    for (int r = wid; r < nrows; r += NWARP)
        warp_readout(sX + r*DD, sB1, sW2v, bias2,
                     out + ((size_t)(b*(STEPS+1) + 0))*NN + base + r, lane);

    for (int s = 0; s < STEPS; ++s) {
        const float dt = (float)(s+1)*0.1f - (float)s*0.1f;
        for (int st = 0; st < 4; ++st) {
            for (int l = 0; l < 2; ++l) {
                // ======= Phase A: h = x@W, e_src, e_dst (own rows only) ===
                {
                    const float* Wl = sW + l*DD*DD;
                    const float2* w2p = reinterpret_cast<const float2*>(Wl);
                    const int r0 = wid * 2;
                    if (r0 < nrows) {
                        int rl0 = r0;
                        int rl1 = (r0 + 1 > nrows-1) ? nrows-1 : r0 + 1;
                        float a0x=0,a0y=0,a1x=0,a1y=0;
                        const float4* x4 = reinterpret_cast<const float4*>(sX);
                        #pragma unroll 4
                        for (int k4 = 0; k4 < 16; ++k4) {
                            float4 x0 = x4[rl0*16 + k4];
                            float4 x1 = x4[rl1*16 + k4];
                            #pragma unroll
                            for (int kk = 0; kk < 4; ++kk) {
                                float2 w = w2p[(k4*4+kk)*32 + lane];
                                float c0 = f4c(x0,kk), c1 = f4c(x1,kk);
                                a0x += c0*w.x; a0y += c0*w.y;
                                a1x += c1*w.x; a1y += c1*w.y;
                            }
                        }
                        float ax[QSLOT] = {a0x, a1x};
                        float ay[QSLOT] = {a0y, a1y};
                        #pragma unroll
                        for (int q = 0; q < QSLOT; ++q) {
                            if (r0 + q >= nrows) break;
                            const int row = base + r0 + q;
                            float* hp = g_h[l] + bo + (size_t)row*DD;
                            __stcg(reinterpret_cast<float2*>(hp + 2*lane),
                                   make_float2(ax[q], ay[q]));
                            float ves = ax[q]*sAS[l*DD + 2*lane] + ay[q]*sAS[l*DD + 2*lane + 1];
                            float ved = ax[q]*sAD[l*DD + 2*lane] + ay[q]*sAD[l*DD + 2*lane + 1];
                            #pragma unroll
                            for (int off = 4; off; off >>= 1) {
                                ves += __shfl_down_sync(0xffffffffu, ves, off, 8);
                                ved += __shfl_down_sync(0xffffffffu, ved, off, 8);
                            }
                            if ((lane & 7) == 0) {
                                sEs[(r0 + q)*4 + hsel] = ves;
                                __stcg(g_ed4[l] + ((size_t)b*NN + row)*4 + hsel, ved);
                            }
                        }
                    }
                }
                cluster_sync_rel();
                // ======= softmax: 2 rows fused (no shift, ed via L2) ======
                {
                    const float4* edg = reinterpret_cast<const float4*>(
                        g_ed4[l] + (size_t)b*NN*HH);
                    const int r0 = wid * 2;
                    if (r0 < nrows) {
                        const bool hasB = (r0 + 1 < nrows);
                        const int cntA = sCnt[r0];
                        const int cntB = hasB ? sCnt[r0 + 1] : 0;
                        const int c8A = (cntA + 7) & ~7;
                        const int c8B = (cntB + 7) & ~7;
                        const int cmax = (c8A > c8B) ? c8A : c8B;
                        const int* idxA = sIdx + r0 * MAXD;
                        const int* idxB = sIdx + (hasB ? (r0 + 1) : r0) * MAXD;
                        float4* awA = reinterpret_cast<float4*>(sAl)
                                    + (wid*QSLOT + 0) * MAXD;
                        float4* awB = reinterpret_cast<float4*>(sAl)
                                    + (wid*QSLOT + 1) * MAXD;
                        float4 esA = reinterpret_cast<const float4*>(sEs)[r0];
                        float4 esB = hasB
                            ? reinterpret_cast<const float4*>(sEs)[r0 + 1] : esA;
                        for (int j0 = lane; j0 < cmax; j0 += 32) {
                            if (j0 < c8A) {
                                int j = idxA[j0];
                                float4 ev = __ldcg(edg + j);
                                float e0 = esA.x + ev.x; e0 = fmaxf(e0, 0.2f*e0);
                                float e1 = esA.y + ev.y; e1 = fmaxf(e1, 0.2f*e1);
                                float e2 = esA.z + ev.z; e2 = fmaxf(e2, 0.2f*e2);
                                float e3 = esA.w + ev.w; e3 = fmaxf(e3, 0.2f*e3);
                                float p0 = __expf(e0), p1 = __expf(e1);
                                float p2 = __expf(e2), p3 = __expf(e3);
                                if (j0 >= cntA) { p0=0.f; p1=0.f; p2=0.f; p3=0.f; }
                                awA[j0] = make_float4(p0, p1, p2, p3);
                            }
                            if (hasB && j0 < c8B) {
                                int j = idxB[j0];
                                float4 ev = __ldcg(edg + j);
                                float e0 = esB.x + ev.x; e0 = fmaxf(e0, 0.2f*e0);
                                float e1 = esB.y + ev.y; e1 = fmaxf(e1, 0.2f*e1);
                                float e2 = esB.z + ev.z; e2 = fmaxf(e2, 0.2f*e2);
                                float e3 = esB.w + ev.w; e3 = fmaxf(e3, 0.2f*e3);
                                float p0 = __expf(e0), p1 = __expf(e1);
                                float p2 = __expf(e2), p3 = __expf(e3);
                                if (j0 >= cntB) { p0=0.f; p1=0.f; p2=0.f; p3=0.f; }
                                awB[j0] = make_float4(p0, p1, p2, p3);
                            }
                        }
                    }
                }
                // ======= Phase B: SpMM from L2 (h via __ldcg, unroll 8) ===
                {
                    const float2* hg = reinterpret_cast<const float2*>(g_h[l] + bo);
                    #pragma unroll
                    for (int q = 0; q < QSLOT; ++q) {
                        const int r = 2*wid + q;
                        if (r >= nrows) break;
                        const int cnt8 = (sCnt[r] + 7) & ~7;
                        const int* idxr = sIdx + r * MAXD;
                        const float* awf = sAl + (wid*QSLOT + q) * MAXD * 4;
                        float acc0 = 0.f, acc1 = 0.f, ssum = 0.f;
                        for (int j0 = 0; j0 < cnt8; j0 += 8) {
                            int jj[8]; float al[8]; float2 hv[8];
                            #pragma unroll
                            for (int u = 0; u < 8; ++u) jj[u] = idxr[j0+u];
                            #pragma unroll
                            for (int u = 0; u < 8; ++u)
                                al[u] = awf[(j0+u)*4 + hsel];
                            #pragma unroll
                            for (int u = 0; u < 8; ++u)
                                hv[u] = __ldcg(hg + jj[u]*32 + lane);
                            #pragma unroll
                            for (int u = 0; u < 8; ++u) {
                                acc0 += al[u]*hv[u].x;
                                acc1 += al[u]*hv[u].y;
                                ssum += al[u];
                            }
                        }
                        const float inv = 1.f / ssum;
                        float k0 = acc0 * inv;
                        float k1 = acc1 * inv;
                        // ---- fused epilogue (registers -> sX, own row) ----
                        float2* xr2 = reinterpret_cast<float2*>(sX + r*DD) + lane;
                        if (l == 0) {
                            float2 xv;
                            xv.x = (k0 > 0.f) ? k0 : (__expf(k0) - 1.f);
                            xv.y = (k1 > 0.f) ? k1 : (__expf(k1) - 1.f);
                            *xr2 = xv;
                        } else {
                            if (st == 0) { accR[q][0] = k0; accR[q][1] = k1; }
                            else {
                                float w = (st == 3) ? 1.f : 2.f;
                                accR[q][0] += w * k0; accR[q][1] += w * k1;
                            }
                            if (st < 3) {
                                float cc = (st == 2) ? dt : 0.5f * dt;
                                *xr2 = make_float2(yR[q][0] + cc * k0,
                                                   yR[q][1] + cc * k1);
                            } else {
                                yR[q][0] += dt * (1.f/6.f) * accR[q][0];
                                yR[q][1] += dt * (1.f/6.f) * accR[q][1];
                                *xr2 = make_float2(yR[q][0], yR[q][1]);
                            }
                        }
                    }
                }
            } // l
        } // st
        // ---- readout for t = s+1 (sX holds y; cross-warp read) ----
        __syncthreads();
        for (int r = wid; r < nrows; r += NWARP)
            warp_readout(sX + r*DD, sB1, sW2v, bias2,
                         out + ((size_t)(b*(STEPS+1) + s + 1))*NN + base + r, lane);
        // next cluster barrier orders these reads vs future sX writes
    } // s
}

extern "C" void kernel_launch(void* const* d_in, const int* in_sizes, int n_in,
                              void* d_out, int out_size)
{
    const float* y0    = (const float*)d_in[0];
    const float* graph = (const float*)d_in[1];
    const float* Wg    = (const float*)d_in[2];
    const float* a_src = (const float*)d_in[3];
    const float* a_dst = (const float*)d_in[4];
    const float* W1    = (const float*)d_in[5];
    const float* b1    = (const float*)d_in[6];
    const float* W2    = (const float*)d_in[7];
    const float* b2    = (const float*)d_in[8];
    float* out = (float*)d_out;

    cudaFuncSetAttribute(ode_kernel,
                         cudaFuncAttributeMaxDynamicSharedMemorySize, SMEM_BYTES);
    cudaFuncSetAttribute(ode_kernel,
                         cudaFuncAttributeNonPortableClusterSizeAllowed, 1);
    prep_kernel<<<41, 256>>>(graph, W1);
    ode_kernel<<<BB*CLX, TPB, SMEM_BYTES>>>(y0, Wg, a_src, a_dst, b1, W2, b2, out);
}